// round 1
// baseline (speedup 1.0000x reference)
#include <cuda_runtime.h>
#include <cuda_bf16.h>
#include <cstdint>

// Problem constants (from reference setup_inputs): N=50000, E=600000, D=128, NF=3, V=8
#define D_DIM 128
#define NF_DIM 3
#define V_DIM 8
#define MAX_N 50000

// Scratch (device globals; no allocation allowed)
__device__ float g_acc[MAX_N * D_DIM];   // accumulator: nfeat + sum of messages
__device__ float g_deg[MAX_N];           // degree + 1

// ---------------------------------------------------------------------------
// K0: init accumulator with nfeat, degree with 1.0
// ---------------------------------------------------------------------------
__global__ void init_kernel(const float* __restrict__ nfeat, int N) {
    int total4 = N * (D_DIM / 4);
    float4* acc4 = reinterpret_cast<float4*>(g_acc);
    const float4* nf4 = reinterpret_cast<const float4*>(nfeat);
    for (int i = blockIdx.x * blockDim.x + threadIdx.x; i < total4;
         i += gridDim.x * blockDim.x) {
        acc4[i] = nf4[i];
    }
    for (int i = blockIdx.x * blockDim.x + threadIdx.x; i < N;
         i += gridDim.x * blockDim.x) {
        g_deg[i] = 1.0f;
    }
}

// ---------------------------------------------------------------------------
// K1: edge scatter. One warp per edge. Each lane handles 4 contiguous dims.
//     m = nfeat[src] + sum_f edge_emb[f, idx_f]  -> red.v4 onto g_acc[dst]
// ---------------------------------------------------------------------------
__global__ void edge_scatter_kernel(const float* __restrict__ nfeat,
                                    const int* __restrict__ src,
                                    const int* __restrict__ dst,
                                    const int* __restrict__ eidx,
                                    const float* __restrict__ emb,
                                    int E) {
    int e = blockIdx.x * (blockDim.x >> 5) + (threadIdx.x >> 5);
    if (e >= E) return;
    int lane = threadIdx.x & 31;

    int s  = __ldg(src + e);
    int d  = __ldg(dst + e);
    int i0 = __ldg(eidx + e * NF_DIM + 0);
    int i1 = __ldg(eidx + e * NF_DIM + 1);
    int i2 = __ldg(eidx + e * NF_DIM + 2);

    int c = lane * 4;
    float4 v  = __ldg(reinterpret_cast<const float4*>(nfeat + (size_t)s * D_DIM + c));
    float4 e0 = __ldg(reinterpret_cast<const float4*>(emb + ((0 * V_DIM + i0) * D_DIM) + c));
    float4 e1 = __ldg(reinterpret_cast<const float4*>(emb + ((1 * V_DIM + i1) * D_DIM) + c));
    float4 e2 = __ldg(reinterpret_cast<const float4*>(emb + ((2 * V_DIM + i2) * D_DIM) + c));

    float mx = v.x + e0.x + e1.x + e2.x;
    float my = v.y + e0.y + e1.y + e2.y;
    float mz = v.z + e0.z + e1.z + e2.z;
    float mw = v.w + e0.w + e1.w + e2.w;

    float* p = g_acc + (size_t)d * D_DIM + c;
    asm volatile("red.global.add.v4.f32 [%0], {%1, %2, %3, %4};"
                 :: "l"(p), "f"(mx), "f"(my), "f"(mz), "f"(mw) : "memory");

    if (lane == 0) {
        atomicAdd(&g_deg[d], 1.0f);  // no return use -> REDG
    }
}

// ---------------------------------------------------------------------------
// K2: out = (g_acc / g_deg) @ W + b
//     Block: 64 rows x 128 cols. blockDim (16,8) = 128 threads.
//     Each thread: 8 rows (interleaved stride 8) x 8 cols.
//     W (64KB) + h-tile (64x132 fp32, 33KB) staged in dynamic shared (99KB).
// ---------------------------------------------------------------------------
#define HS 132  // h-tile row stride in floats (conflict-free for row-diff 1)

__global__ void gemm_kernel(const float* __restrict__ W,
                            const float* __restrict__ b,
                            float* __restrict__ out, int N) {
    extern __shared__ float sm[];
    float* Wsh = sm;                  // 128*128 floats
    float* hsh = sm + D_DIM * D_DIM;  // 64 * HS floats

    int tx = threadIdx.x;   // 0..15 (col groups of 8)
    int ty = threadIdx.y;   // 0..7  (row within group-of-8)
    int tid = ty * 16 + tx; // 0..127
    int row0 = blockIdx.x * 64;

    // Stage W into shared
    {
        const float4* W4 = reinterpret_cast<const float4*>(W);
        float4* Wsh4 = reinterpret_cast<float4*>(Wsh);
        #pragma unroll
        for (int i = tid; i < (D_DIM * D_DIM) / 4; i += 128)
            Wsh4[i] = __ldg(W4 + i);
    }

    // Stage h tile: h = acc * (1/deg)
    for (int i = tid; i < 64 * (D_DIM / 4); i += 128) {
        int lr = i >> 5;        // local row 0..63
        int cc = (i & 31) * 4;  // col 0..124 step 4
        int row = row0 + lr;
        float4 v = make_float4(0.f, 0.f, 0.f, 0.f);
        if (row < N) {
            v = *reinterpret_cast<const float4*>(g_acc + (size_t)row * D_DIM + cc);
            float invd = 1.0f / g_deg[row];
            v.x *= invd; v.y *= invd; v.z *= invd; v.w *= invd;
        }
        *reinterpret_cast<float4*>(hsh + lr * HS + cc) = v;
    }
    __syncthreads();

    float acc[8][8];
    #pragma unroll
    for (int r = 0; r < 8; r++)
        #pragma unroll
        for (int c = 0; c < 8; c++) acc[r][c] = 0.f;

    int colb = tx * 8;

    #pragma unroll 8
    for (int k = 0; k < D_DIM; k++) {
        float4 wa = *reinterpret_cast<const float4*>(Wsh + k * D_DIM + colb);
        float4 wb = *reinterpret_cast<const float4*>(Wsh + k * D_DIM + colb + 4);
        float hr[8];
        #pragma unroll
        for (int r = 0; r < 8; r++)
            hr[r] = hsh[(ty + r * 8) * HS + k];  // rows interleaved by 8
        #pragma unroll
        for (int r = 0; r < 8; r++) {
            acc[r][0] += hr[r] * wa.x;
            acc[r][1] += hr[r] * wa.y;
            acc[r][2] += hr[r] * wa.z;
            acc[r][3] += hr[r] * wa.w;
            acc[r][4] += hr[r] * wb.x;
            acc[r][5] += hr[r] * wb.y;
            acc[r][6] += hr[r] * wb.z;
            acc[r][7] += hr[r] * wb.w;
        }
    }

    float4 b0 = __ldg(reinterpret_cast<const float4*>(b + colb));
    float4 b1 = __ldg(reinterpret_cast<const float4*>(b + colb + 4));

    #pragma unroll
    for (int r = 0; r < 8; r++) {
        int row = row0 + ty + r * 8;
        if (row < N) {
            float4 o0 = make_float4(acc[r][0] + b0.x, acc[r][1] + b0.y,
                                    acc[r][2] + b0.z, acc[r][3] + b0.w);
            float4 o1 = make_float4(acc[r][4] + b1.x, acc[r][5] + b1.y,
                                    acc[r][6] + b1.z, acc[r][7] + b1.w);
            *reinterpret_cast<float4*>(out + (size_t)row * D_DIM + colb)     = o0;
            *reinterpret_cast<float4*>(out + (size_t)row * D_DIM + colb + 4) = o1;
        }
    }
}

// ---------------------------------------------------------------------------
// Launch
// Inputs (metadata order): nfeat[N*D] f32, src[E] i32, dst[E] i32,
//   efeat_idx[E*3] i32, edge_emb[3*8*128] f32, W[128*128] f32, b[128] f32
// Output: float[N*128]
// ---------------------------------------------------------------------------
extern "C" void kernel_launch(void* const* d_in, const int* in_sizes, int n_in,
                              void* d_out, int out_size) {
    const float* nfeat = (const float*)d_in[0];
    const int*   src   = (const int*)d_in[1];
    const int*   dst   = (const int*)d_in[2];
    const int*   eidx  = (const int*)d_in[3];
    const float* emb   = (const float*)d_in[4];
    const float* W     = (const float*)d_in[5];
    const float* b     = (const float*)d_in[6];
    float* out = (float*)d_out;

    int N = in_sizes[0] / D_DIM;
    int E = in_sizes[1];

    // K0: init
    init_kernel<<<592, 256>>>(nfeat, N);

    // K1: edge scatter (1 warp per edge, 8 edges per 256-thread block)
    int eb = (E + 7) / 8;
    edge_scatter_kernel<<<eb, 256>>>(nfeat, src, dst, eidx, emb, E);

    // K2: GEMM + bias
    int smem = (D_DIM * D_DIM + 64 * HS) * (int)sizeof(float);  // 99328 B
    cudaFuncSetAttribute(gemm_kernel, cudaFuncAttributeMaxDynamicSharedMemorySize, smem);
    int gb = (N + 63) / 64;
    gemm_kernel<<<gb, dim3(16, 8), smem>>>(W, b, out, N);
}